// round 6
// baseline (speedup 1.0000x reference)
#include <cuda_runtime.h>
#include <cuda_bf16.h>

typedef unsigned long long ull;

// Problem constants (fixed by the dataset)
#define N_NODES 16384      // B*n = 8*2048
#define K_EDGE  16
#define CIN     64
#define HID     64
#define OUTC    128
#define L6      6
#define KV      400        // 384 (6*64 layers) + 6 (Cl) + 10 zero pad
#define EPS     1e-5f

// ---------------- scratch (device globals; no allocations) ----------------
__device__ float g_V[N_NODES * KV];        // [t][l*64+c], cols 384..389 = Cl, 390..399 = 0
__device__ float g_Y[N_NODES * HID];       // y_pre (before BN1)
__device__ float g_part1[2 * 128 * HID];   // per-K2-block BN partials (sum, sumsq)
__device__ float g_part2[2 * 128 * OUTC];  // per-K4-block BN partials

// ---------------- f32x2 helpers ----------------
__device__ __forceinline__ void ffma2(ull& d, ull a, ull b) {
    asm("fma.rn.f32x2 %0, %1, %2, %3;" : "=l"(d) : "l"(a), "l"(b), "l"(d));
}
__device__ __forceinline__ ull dup2(float v) {
    ull r; asm("mov.b64 %0, {%1, %1};" : "=l"(r) : "f"(v)); return r;
}
__device__ __forceinline__ float2 unpk(ull v) {
    float2 r; asm("mov.b64 {%0, %1}, %2;" : "=f"(r.x), "=f"(r.y) : "l"(v)); return r;
}

// ---------------- K1: per-target edge phase ----------------
// grid = N_NODES/4 blocks, 256 threads (4 targets per block).
__global__ __launch_bounds__(256) void k1_edge(
    const float* __restrict__ x, const float* __restrict__ p,
    const int* __restrict__ sid)
{
    __shared__ float s_coef[4][K_EDGE][8];  // [tgt][edge][layer] (padded to 8)
    __shared__ int   s_sid[4][K_EDGE];

    const int tid  = threadIdx.x;
    const int w    = tid >> 5;
    const int lane = tid & 31;

    if (w < 4) {
        const int t   = blockIdx.x * 4 + w;
        const int j   = lane & 15;
        const bool act = lane < 16;
        const int s   = sid[t * K_EDGE + j];

        float dx = 0.f, dy = 0.f, dz = 0.f, dis = 0.f;
        if (act) {
            const float px = p[t*3+0], py = p[t*3+1], pz = p[t*3+2];
            dx = p[s*3+0] - px;
            dy = p[s*3+1] - py;
            dz = p[s*3+2] - pz;
            dis = fmaxf(sqrtf(dx*dx + dy*dy + dz*dz), 1e-16f);
            s_sid[w][j] = s;
        }
        float m = dis;
        #pragma unroll
        for (int off = 16; off; off >>= 1)
            m = fmaxf(m, __shfl_xor_sync(0xffffffffu, m, off));
        const float pr  = 1.1f * m;
        float pdv = act ? (pr - dis) * (pr - dis) : 0.f;
        float ssum = pdv;
        #pragma unroll
        for (int off = 16; off; off >>= 1)
            ssum += __shfl_xor_sync(0xffffffffu, ssum, off);

        if (act) {
            const float wgt = pdv / ssum;
            const float inv = 1.f / dis;
            const float c0 = cosf(dx * inv);
            const float c1 = cosf(dy * inv);
            const float c2 = cosf(dz * inv);
            float a[6] = {0.f, 0.f, 0.f, 0.f, 0.f, 0.f};
            a[    ((dx > 0.f) ? 1 : 0)] = c0 * c0;
            a[2 + ((dy > 0.f) ? 1 : 0)] = c1 * c1;
            a[4 + ((dz > 0.f) ? 1 : 0)] = c2 * c2;
            #pragma unroll
            for (int l = 0; l < 6; l++) s_coef[w][j][l] = wgt * a[l];
        }
    }
    __syncthreads();

    // Cl sums into g_V cols 384..389; zero pad cols 390..399
    if (tid < 24) {
        const int tw = tid / 6, l = tid - tw * 6;
        float cl = 0.f;
        #pragma unroll
        for (int j = 0; j < K_EDGE; j++) cl += s_coef[tw][j][l];
        g_V[(size_t)(blockIdx.x * 4 + tw) * KV + 384 + l] = cl;
    }
    if (tid < 40) {
        const int tw = tid / 10, z = tid - tw * 10;
        g_V[(size_t)(blockIdx.x * 4 + tw) * KV + 390 + z] = 0.f;
    }

    // V accumulation: 64 threads per target, each thread owns channel c, all 6 layers
    const int grp = tid >> 6;          // target within block
    const int c   = tid & 63;          // channel
    const int t   = blockIdx.x * 4 + grp;
    const float xt = x[t * CIN + c];
    float acc[6] = {0.f, 0.f, 0.f, 0.f, 0.f, 0.f};
    #pragma unroll
    for (int j = 0; j < K_EDGE; j++) {
        const float ev = x[s_sid[grp][j] * CIN + c] - xt;
        const float4 c01 = *(const float4*)&s_coef[grp][j][0];
        const float2 c2  = *(const float2*)&s_coef[grp][j][4];
        acc[0] = fmaf(c01.x, ev, acc[0]);
        acc[1] = fmaf(c01.y, ev, acc[1]);
        acc[2] = fmaf(c01.z, ev, acc[2]);
        acc[3] = fmaf(c01.w, ev, acc[3]);
        acc[4] = fmaf(c2.x,  ev, acc[4]);
        acc[5] = fmaf(c2.y,  ev, acc[5]);
    }
    float* vp = g_V + (size_t)t * KV + c;
    #pragma unroll
    for (int l = 0; l < 6; l++) vp[l * 64] = acc[l];
}

// ---------------- K2: y_pre = V(16384x400) @ [Wcat; lins_b; 0] ----------------
// BM=128, BN=64, BK=16, 256 threads, pair-over-M f32x2, double-buffered.
#define K2_STEPS 25
__global__ __launch_bounds__(256) void k2_gemm(
    const float* __restrict__ W2,   // lins_W viewed as (384, 64)
    const float* __restrict__ lb)   // lins_b (6, 64)
{
    __shared__ float As[2][16 * 130];      // [stage][kk*130 + m], m contiguous
    __shared__ ull   Bd[2][16 * 70];       // [stage][kk*70 + (j&3)*17 + (j>>2)] dup pairs
    __shared__ float s_m[16][64], s_v[16][64];

    const int tid = threadIdx.x;
    const int r0  = blockIdx.x * 128;
    const int tx  = tid & 15, ty = tid >> 4;
    const int lkk = tid & 15, lm = tid >> 4;   // A loader
    const int bkk = tid >> 6, bj = tid & 63;   // B loader

    // initial tile 0
    #pragma unroll
    for (int jj = 0; jj < 8; jj++) {
        const int m = lm + 16 * jj;
        As[0][lkk * 130 + m] = g_V[(size_t)(r0 + m) * KV + lkk];
    }
    #pragma unroll
    for (int jj = 0; jj < 4; jj++) {
        const int kk = bkk + 4 * jj;
        Bd[0][kk * 70 + (bj & 3) * 17 + (bj >> 2)] = dup2(W2[kk * 64 + bj]);
    }
    __syncthreads();

    ull acc[4][4];
    #pragma unroll
    for (int i = 0; i < 4; i++)
        #pragma unroll
        for (int j = 0; j < 4; j++) acc[i][j] = 0ULL;

    for (int s = 0; s < K2_STEPS; s++) {
        const int st = s & 1;
        const bool more = (s + 1 < K2_STEPS);
        float ra[8], rb[4];
        if (more) {
            const int k0n = (s + 1) * 16;
            #pragma unroll
            for (int jj = 0; jj < 8; jj++)
                ra[jj] = g_V[(size_t)(r0 + lm + 16 * jj) * KV + k0n + lkk];
            #pragma unroll
            for (int jj = 0; jj < 4; jj++) {
                const int row = k0n + bkk + 4 * jj;
                rb[jj] = (row < 384) ? W2[row * 64 + bj]
                       : (row < 390) ? lb[(row - 384) * 64 + bj] : 0.f;
            }
        }
        #pragma unroll
        for (int kk = 0; kk < 16; kk++) {
            const ull* ap = (const ull*)&As[st][kk * 130];
            ull a0 = ap[ty * 4 + 0], a1 = ap[ty * 4 + 1];
            ull a2 = ap[ty * 4 + 2], a3 = ap[ty * 4 + 3];
            const ull* bp = &Bd[st][kk * 70 + tx];
            ull b0 = bp[0], b1 = bp[17], b2 = bp[34], b3 = bp[51];
            ffma2(acc[0][0], a0, b0); ffma2(acc[0][1], a0, b1);
            ffma2(acc[0][2], a0, b2); ffma2(acc[0][3], a0, b3);
            ffma2(acc[1][0], a1, b0); ffma2(acc[1][1], a1, b1);
            ffma2(acc[1][2], a1, b2); ffma2(acc[1][3], a1, b3);
            ffma2(acc[2][0], a2, b0); ffma2(acc[2][1], a2, b1);
            ffma2(acc[2][2], a2, b2); ffma2(acc[2][3], a2, b3);
            ffma2(acc[3][0], a3, b0); ffma2(acc[3][1], a3, b1);
            ffma2(acc[3][2], a3, b2); ffma2(acc[3][3], a3, b3);
        }
        if (more) {
            #pragma unroll
            for (int jj = 0; jj < 8; jj++)
                As[st ^ 1][lkk * 130 + lm + 16 * jj] = ra[jj];
            #pragma unroll
            for (int jj = 0; jj < 4; jj++)
                Bd[st ^ 1][(bkk + 4 * jj) * 70 + (bj & 3) * 17 + (bj >> 2)] = dup2(rb[jj]);
        }
        __syncthreads();
    }

    // epilogue: store y_pre + BN1 partials
    float cs[4] = {0.f, 0.f, 0.f, 0.f}, cs2[4] = {0.f, 0.f, 0.f, 0.f};
    #pragma unroll
    for (int pi = 0; pi < 4; pi++) {
        const int re = r0 + ty * 8 + 2 * pi;
        float lo[4], hi[4];
        #pragma unroll
        for (int jp = 0; jp < 4; jp++) {
            const float2 v = unpk(acc[pi][jp]);
            lo[jp] = v.x; hi[jp] = v.y;
            cs[jp]  += v.x + v.y;
            cs2[jp] += v.x * v.x + v.y * v.y;
        }
        *(float4*)&g_Y[(size_t)re * HID + tx * 4] =
            make_float4(lo[0], lo[1], lo[2], lo[3]);
        *(float4*)&g_Y[(size_t)(re + 1) * HID + tx * 4] =
            make_float4(hi[0], hi[1], hi[2], hi[3]);
    }
    #pragma unroll
    for (int jp = 0; jp < 4; jp++) {
        s_m[ty][tx * 4 + jp] = cs[jp];
        s_v[ty][tx * 4 + jp] = cs2[jp];
    }
    __syncthreads();
    if (tid < 64) {
        float s = 0.f, s2 = 0.f;
        #pragma unroll
        for (int g = 0; g < 16; g++) { s += s_m[g][tid]; s2 += s_v[g][tid]; }
        g_part1[blockIdx.x * 64 + tid] = s;
        g_part1[8192 + blockIdx.x * 64 + tid] = s2;
    }
}

// ---------------- K4: out_pre = [x | bnrelu(y_pre)] @ [W1; W2] + biases ----
// BM=128, BN=128, BK=16, 256 threads, pair-over-M f32x2, double-buffered.
// Dynamic shared memory (70912 B) — carve offsets:
#define O_AS  0        // float[2][2080]   16640 B
#define O_BD  16640    // ull[2][2176]     34816 B
#define O_SM  51456    // float[2048]       8192 B
#define O_SV  59648    // float[2048]       8192 B
#define O_SC  67840    // float[64]
#define O_SH  68096    // float[64]
#define O_SB  68352    // float[128]
#define O_R1  68864    // float[256]
#define O_R2  69888    // float[256]
#define SMEM4 70912

__global__ __launch_bounds__(256) void k4_gemm(
    const float* __restrict__ x,
    const float* __restrict__ w1,  const float* __restrict__ w2,
    const float* __restrict__ b1w, const float* __restrict__ b2w,
    const float* __restrict__ gam1, const float* __restrict__ bet1,
    float* __restrict__ out)
{
    extern __shared__ char dyn[];
    float* Asf    = (float*)(dyn + O_AS);
    ull*   Bdu    = (ull*)  (dyn + O_BD);
    float* s_m    = (float*)(dyn + O_SM);
    float* s_v    = (float*)(dyn + O_SV);
    float* s_sc   = (float*)(dyn + O_SC);
    float* s_sh   = (float*)(dyn + O_SH);
    float* s_bias = (float*)(dyn + O_SB);
    float* s_r1   = (float*)(dyn + O_R1);
    float* s_r2   = (float*)(dyn + O_R2);

    const int tid = threadIdx.x;
    const int r0  = blockIdx.x * 128;

    // prologue: reduce BN1 partials (128 K2 blocks)
    {
        const int ch = tid & 63, q = tid >> 6;
        float s = 0.f, s2 = 0.f;
        #pragma unroll
        for (int b = q * 32; b < q * 32 + 32; b++) {
            s  += g_part1[b * 64 + ch];
            s2 += g_part1[8192 + b * 64 + ch];
        }
        s_r1[q * 64 + ch] = s; s_r2[q * 64 + ch] = s2;
        if (tid < 128) s_bias[tid] = b1w[tid] + b2w[tid];
        __syncthreads();
        if (tid < 64) {
            const float ss  = s_r1[tid] + s_r1[64 + tid] + s_r1[128 + tid] + s_r1[192 + tid];
            const float ss2 = s_r2[tid] + s_r2[64 + tid] + s_r2[128 + tid] + s_r2[192 + tid];
            const float mean = ss * (1.f / (float)N_NODES);
            const float var  = ss2 * (1.f / (float)N_NODES) - mean * mean;
            const float sc = rsqrtf(var + EPS) * gam1[tid];
            s_sc[tid] = sc;
            s_sh[tid] = bet1[tid] - mean * sc;
        }
        __syncthreads();
    }

    const int tx  = tid & 15, ty = tid >> 4;
    const int lkk = tid & 15, lm = tid >> 4;     // A loader
    const int br  = tid >> 7, bh = tid & 127;    // B loader

    // initial tile 0 (x half)
    #pragma unroll
    for (int jj = 0; jj < 8; jj++) {
        const int m = lm + 16 * jj;
        Asf[lkk * 130 + m] = x[(size_t)(r0 + m) * CIN + lkk];
    }
    #pragma unroll
    for (int jj = 0; jj < 8; jj++) {
        const int r = br + 2 * jj;
        Bdu[r * 136 + (bh & 7) * 17 + (bh >> 3)] = dup2(w1[r * OUTC + bh]);
    }
    __syncthreads();

    ull acc[4][8];
    #pragma unroll
    for (int i = 0; i < 4; i++)
        #pragma unroll
        for (int j = 0; j < 8; j++) acc[i][j] = 0ULL;

    #define K4_STEPS 8
    for (int s = 0; s < K4_STEPS; s++) {
        const int st = s & 1;
        const bool more = (s + 1 < K4_STEPS);
        float ra[8], rb[8];
        if (more) {
            const int k0n = (s + 1) * 16;
            const bool xh = (k0n < 64);
            #pragma unroll
            for (int jj = 0; jj < 8; jj++) {
                const int m = lm + 16 * jj;
                if (xh) {
                    ra[jj] = x[(size_t)(r0 + m) * CIN + k0n + lkk];
                } else {
                    const int c = k0n + lkk - 64;
                    const float v = g_Y[(size_t)(r0 + m) * HID + c];
                    ra[jj] = fmaxf(fmaf(v, s_sc[c], s_sh[c]), 0.f);
                }
            }
            #pragma unroll
            for (int jj = 0; jj < 8; jj++) {
                const int r = k0n + br + 2 * jj;
                rb[jj] = xh ? w1[r * OUTC + bh] : w2[(r - 64) * OUTC + bh];
            }
        }
        const float* Ab = Asf + st * 2080;
        const ull*   Bb = Bdu + st * 2176;
        #pragma unroll
        for (int kk = 0; kk < 16; kk++) {
            const ull* ap = (const ull*)(Ab + kk * 130);
            ull a0 = ap[ty * 4 + 0], a1 = ap[ty * 4 + 1];
            ull a2 = ap[ty * 4 + 2], a3 = ap[ty * 4 + 3];
            const ull* bp = Bb + kk * 136 + tx;
            #pragma unroll
            for (int jp = 0; jp < 8; jp++) {
                const ull b = bp[jp * 17];
                ffma2(acc[0][jp], a0, b);
                ffma2(acc[1][jp], a1, b);
                ffma2(acc[2][jp], a2, b);
                ffma2(acc[3][jp], a3, b);
            }
        }
        if (more) {
            float* An = Asf + (st ^ 1) * 2080;
            ull*   Bn = Bdu + (st ^ 1) * 2176;
            #pragma unroll
            for (int jj = 0; jj < 8; jj++)
                An[lkk * 130 + lm + 16 * jj] = ra[jj];
            #pragma unroll
            for (int jj = 0; jj < 8; jj++)
                Bn[(br + 2 * jj) * 136 + (bh & 7) * 17 + (bh >> 3)] = dup2(rb[jj]);
        }
        __syncthreads();
    }

    // epilogue: bias, store, BN2 partials
    float cs[8], cs2[8];
    #pragma unroll
    for (int q = 0; q < 8; q++) { cs[q] = 0.f; cs2[q] = 0.f; }
    #pragma unroll
    for (int pi = 0; pi < 4; pi++) {
        const int re = r0 + ty * 8 + 2 * pi;
        float lo[8], hi[8];
        #pragma unroll
        for (int jp = 0; jp < 8; jp++) {
            const float2 v = unpk(acc[pi][jp]);
            const float bb = s_bias[tx * 8 + jp];
            lo[jp] = v.x + bb; hi[jp] = v.y + bb;
            cs[jp]  += lo[jp] + hi[jp];
            cs2[jp] += lo[jp] * lo[jp] + hi[jp] * hi[jp];
        }
        float* oe = out + (size_t)re * OUTC + tx * 8;
        float* oo = out + (size_t)(re + 1) * OUTC + tx * 8;
        *(float4*)oe       = make_float4(lo[0], lo[1], lo[2], lo[3]);
        *(float4*)(oe + 4) = make_float4(lo[4], lo[5], lo[6], lo[7]);
        *(float4*)oo       = make_float4(hi[0], hi[1], hi[2], hi[3]);
        *(float4*)(oo + 4) = make_float4(hi[4], hi[5], hi[6], hi[7]);
    }
    #pragma unroll
    for (int jp = 0; jp < 8; jp++) {
        s_m[ty * 128 + tx * 8 + jp] = cs[jp];
        s_v[ty * 128 + tx * 8 + jp] = cs2[jp];
    }
    __syncthreads();
    if (tid < 128) {
        float s = 0.f, s2 = 0.f;
        #pragma unroll
        for (int g = 0; g < 16; g++) { s += s_m[g * 128 + tid]; s2 += s_v[g * 128 + tid]; }
        g_part2[blockIdx.x * 128 + tid] = s;
        g_part2[16384 + blockIdx.x * 128 + tid] = s2;
    }
}

// ---------------- K6: reduce BN2 partials + BN + relu ----------------
// grid = 128 blocks, 512 threads; each block handles 128 rows.
__global__ __launch_bounds__(512) void k6_final(
    float* __restrict__ out,
    const float* __restrict__ gam2, const float* __restrict__ bet2)
{
    __shared__ float s_sc[128], s_sh[128];
    __shared__ float s_r[4][128], s_r2[4][128];

    const int tid = threadIdx.x;
    const int ch = tid & 127, q = tid >> 7;
    float s = 0.f, s2 = 0.f;
    #pragma unroll
    for (int b = q * 32; b < q * 32 + 32; b++) {
        s  += g_part2[b * 128 + ch];
        s2 += g_part2[16384 + b * 128 + ch];
    }
    s_r[q][ch] = s; s_r2[q][ch] = s2;
    __syncthreads();
    if (tid < 128) {
        const float ss  = s_r[0][tid] + s_r[1][tid] + s_r[2][tid] + s_r[3][tid];
        const float ss2 = s_r2[0][tid] + s_r2[1][tid] + s_r2[2][tid] + s_r2[3][tid];
        const float mean = ss * (1.f / (float)N_NODES);
        const float var  = ss2 * (1.f / (float)N_NODES) - mean * mean;
        const float sc = rsqrtf(var + EPS) * gam2[tid];
        s_sc[tid] = sc;
        s_sh[tid] = bet2[tid] - mean * sc;
    }
    __syncthreads();

    float4* o4 = (float4*)(out + (size_t)blockIdx.x * 128 * OUTC);
    #pragma unroll
    for (int i = tid; i < 128 * 32; i += 512) {
        const int c = (i & 31) * 4;
        float4 v = o4[i];
        v.x = fmaxf(fmaf(v.x, s_sc[c + 0], s_sh[c + 0]), 0.f);
        v.y = fmaxf(fmaf(v.y, s_sc[c + 1], s_sh[c + 1]), 0.f);
        v.z = fmaxf(fmaf(v.z, s_sc[c + 2], s_sh[c + 2]), 0.f);
        v.w = fmaxf(fmaf(v.w, s_sc[c + 3], s_sh[c + 3]), 0.f);
        o4[i] = v;
    }
}

// ---------------- launcher ----------------
extern "C" void kernel_launch(void* const* d_in, const int* in_sizes, int n_in,
                              void* d_out, int out_size)
{
    const float* x   = (const float*)d_in[0];
    const float* p   = (const float*)d_in[1];
    const int*   sid = (const int*)d_in[2];
    // d_in[3] = tid_euc (implicit arange/k grouping; unused)

    int o = 4;
    if (n_in >= 16 && in_sizes[4] == 1) o = 6;

    const float* lins_W = (const float*)d_in[o];
    const float* lins_b = (const float*)d_in[o + 1];
    const float* lin1_W = (const float*)d_in[o + 2];
    const float* lin1_b = (const float*)d_in[o + 3];
    const float* lin2_W = (const float*)d_in[o + 4];
    const float* lin2_b = (const float*)d_in[o + 5];
    const float* g1     = (const float*)d_in[o + 6];
    const float* b1     = (const float*)d_in[o + 7];
    const float* g2     = (const float*)d_in[o + 8];
    const float* b2     = (const float*)d_in[o + 9];
    float* out = (float*)d_out;

    static bool attr_set = false;
    if (!attr_set) {
        cudaFuncSetAttribute(k4_gemm, cudaFuncAttributeMaxDynamicSharedMemorySize, SMEM4);
        attr_set = true;
    }

    k1_edge<<<N_NODES / 4, 256>>>(x, p, sid);
    k2_gemm<<<N_NODES / 128, 256>>>(lins_W, lins_b);
    k4_gemm<<<N_NODES / 128, 256, SMEM4>>>(x, lin1_W, lin2_W, lin1_b, lin2_b, g1, b1, out);
    k6_final<<<N_NODES / 128, 512>>>(out, g2, b2);
}

// round 7
// speedup vs baseline: 1.5347x; 1.5347x over previous
#include <cuda_runtime.h>
#include <cuda_bf16.h>

typedef unsigned long long ull;

// Problem constants (fixed by the dataset)
#define N_NODES 16384      // B*n = 8*2048
#define K_EDGE  16
#define CIN     64
#define HID     64
#define OUTC    128
#define L6      6
#define KV      384        // 6*64
#define EPS     1e-5f
#define NPB     256        // partial-stat block count (grid of k2/k4)

// ---------------- scratch (device globals; no allocations) ----------------
__device__ float g_V[N_NODES * KV];        // [t][l*64+c]
__device__ float g_Cl[N_NODES * L6];       // per-target coefficient sums
__device__ float g_Y[N_NODES * HID];       // y_pre (before BN1)
__device__ float g_part1[2 * NPB * HID];   // per-k2-block BN partials (sum, sumsq)
__device__ float g_part2[2 * NPB * OUTC];  // per-k4-block BN partials

// ---------------- f32x2 helpers ----------------
__device__ __forceinline__ void ffma2(ull& d, ull a, ull b) {
    asm("fma.rn.f32x2 %0, %1, %2, %3;" : "=l"(d) : "l"(a), "l"(b), "l"(d));
}
__device__ __forceinline__ float2 unpk(ull v) {
    float2 r; asm("mov.b64 {%0, %1}, %2;" : "=f"(r.x), "=f"(r.y) : "l"(v)); return r;
}

// ---------------- K1: per-target edge phase ----------------
// grid = N_NODES/4 blocks, 256 threads (4 targets per block).
__global__ __launch_bounds__(256) void k1_edge(
    const float* __restrict__ x, const float* __restrict__ p,
    const int* __restrict__ sid)
{
    __shared__ float s_coef[4][K_EDGE][8];  // [tgt][edge][layer] (padded to 8)
    __shared__ int   s_sid[4][K_EDGE];

    const int tid  = threadIdx.x;
    const int w    = tid >> 5;
    const int lane = tid & 31;

    if (w < 4) {
        const int t   = blockIdx.x * 4 + w;
        const int j   = lane & 15;
        const bool act = lane < 16;
        const int s   = sid[t * K_EDGE + j];

        float dx = 0.f, dy = 0.f, dz = 0.f, dis = 0.f;
        if (act) {
            const float px = p[t*3+0], py = p[t*3+1], pz = p[t*3+2];
            dx = p[s*3+0] - px;
            dy = p[s*3+1] - py;
            dz = p[s*3+2] - pz;
            dis = fmaxf(sqrtf(dx*dx + dy*dy + dz*dz), 1e-16f);
            s_sid[w][j] = s;
        }
        float m = dis;
        #pragma unroll
        for (int off = 16; off; off >>= 1)
            m = fmaxf(m, __shfl_xor_sync(0xffffffffu, m, off));
        const float pr  = 1.1f * m;
        float pdv = act ? (pr - dis) * (pr - dis) : 0.f;
        float ssum = pdv;
        #pragma unroll
        for (int off = 16; off; off >>= 1)
            ssum += __shfl_xor_sync(0xffffffffu, ssum, off);

        if (act) {
            const float wgt = pdv / ssum;
            const float inv = 1.f / dis;
            const float c0 = cosf(dx * inv);
            const float c1 = cosf(dy * inv);
            const float c2 = cosf(dz * inv);
            float a[6] = {0.f, 0.f, 0.f, 0.f, 0.f, 0.f};
            a[    ((dx > 0.f) ? 1 : 0)] = c0 * c0;
            a[2 + ((dy > 0.f) ? 1 : 0)] = c1 * c1;
            a[4 + ((dz > 0.f) ? 1 : 0)] = c2 * c2;
            #pragma unroll
            for (int l = 0; l < 6; l++) s_coef[w][j][l] = wgt * a[l];
        }
    }
    __syncthreads();

    // Cl sums (24 threads: 4 targets x 6 layers)
    if (tid < 24) {
        const int tw = tid / 6, l = tid - tw * 6;
        float cl = 0.f;
        #pragma unroll
        for (int j = 0; j < K_EDGE; j++) cl += s_coef[tw][j][l];
        g_Cl[(blockIdx.x * 4 + tw) * L6 + l] = cl;
    }

    // V accumulation: 64 threads per target, each thread owns channel c, all 6 layers
    const int grp = tid >> 6;
    const int c   = tid & 63;
    const int t   = blockIdx.x * 4 + grp;
    const float xt = x[t * CIN + c];
    float acc[6] = {0.f, 0.f, 0.f, 0.f, 0.f, 0.f};
    #pragma unroll
    for (int j = 0; j < K_EDGE; j++) {
        const float ev = x[s_sid[grp][j] * CIN + c] - xt;
        const float4 c01 = *(const float4*)&s_coef[grp][j][0];
        const float2 c2  = *(const float2*)&s_coef[grp][j][4];
        acc[0] = fmaf(c01.x, ev, acc[0]);
        acc[1] = fmaf(c01.y, ev, acc[1]);
        acc[2] = fmaf(c01.z, ev, acc[2]);
        acc[3] = fmaf(c01.w, ev, acc[3]);
        acc[4] = fmaf(c2.x,  ev, acc[4]);
        acc[5] = fmaf(c2.y,  ev, acc[5]);
    }
    float* vp = g_V + (size_t)t * KV + c;
    #pragma unroll
    for (int l = 0; l < 6; l++) vp[l * 64] = acc[l];
}

// ---------------- K2: y_pre = V @ Wcat + Cl @ lins_b  (+ BN1 partials) ----
// BM=64, BN=64, BK=16, 256 threads, f32x2 (A-dup, B pair-swizzle). grid = 256.
__global__ __launch_bounds__(256) void k2_gemm(
    const float* __restrict__ W2,   // lins_W viewed as (384, 64)
    const float* __restrict__ lb)   // lins_b (6, 64)
{
    __shared__ float Asd[16][130];     // A dup: row m at floats 2m,2m+1
    __shared__ float Bsp[16][64];      // B pair-swizzled: h -> jp*32 + (h>>2)*2 + (h&1)
    __shared__ float sb[6][64];
    __shared__ float s_m[16][64], s_v[16][64];

    const int tid = threadIdx.x;
    const int r0  = blockIdx.x * 64;
    for (int i = tid; i < 384; i += 256) sb[i >> 6][i & 63] = lb[i];

    const int tx = tid & 15;    // col group of 4
    const int ty = tid >> 4;    // row group of 4
    const int lkk = tid & 15, lm = tid >> 4;
    ull acc[4][2];
    #pragma unroll
    for (int i = 0; i < 4; i++) { acc[i][0] = 0ULL; acc[i][1] = 0ULL; }

    for (int k0 = 0; k0 < KV; k0 += 16) {
        __syncthreads();
        #pragma unroll
        for (int jj = 0; jj < 4; jj++) {
            const int m = lm + 16 * jj;
            const float v = g_V[(size_t)(r0 + m) * KV + k0 + lkk];
            *(float2*)&Asd[lkk][2 * m] = make_float2(v, v);
        }
        #pragma unroll
        for (int i = tid; i < 1024; i += 256) {
            const int r = i >> 6, h = i & 63;
            Bsp[r][((h & 3) >> 1) * 32 + (h >> 2) * 2 + (h & 1)] =
                W2[(k0 + r) * 64 + h];
        }
        __syncthreads();
        #pragma unroll
        for (int kk = 0; kk < 16; kk++) {
            const ull* ap = (const ull*)&Asd[kk][0];
            const ull* bp = (const ull*)&Bsp[kk][0];
            ull a0 = ap[ty * 4 + 0], a1 = ap[ty * 4 + 1];
            ull a2 = ap[ty * 4 + 2], a3 = ap[ty * 4 + 3];
            ull b0 = bp[tx], b1 = bp[16 + tx];
            ffma2(acc[0][0], a0, b0); ffma2(acc[0][1], a0, b1);
            ffma2(acc[1][0], a1, b0); ffma2(acc[1][1], a1, b1);
            ffma2(acc[2][0], a2, b0); ffma2(acc[2][1], a2, b1);
            ffma2(acc[3][0], a3, b0); ffma2(acc[3][1], a3, b1);
        }
    }

    // epilogue: + Cl@lins_b, store y_pre, BN1 partials
    float cs[4] = {0.f, 0.f, 0.f, 0.f}, cs2[4] = {0.f, 0.f, 0.f, 0.f};
    #pragma unroll
    for (int i = 0; i < 4; i++) {
        const int r = r0 + ty * 4 + i;
        float cl[6];
        #pragma unroll
        for (int l = 0; l < 6; l++) cl[l] = g_Cl[r * L6 + l];
        const float2 v0 = unpk(acc[i][0]);
        const float2 v1 = unpk(acc[i][1]);
        float vv[4] = {v0.x, v0.y, v1.x, v1.y};
        #pragma unroll
        for (int q = 0; q < 4; q++) {
            const int h = tx * 4 + q;
            #pragma unroll
            for (int l = 0; l < 6; l++) vv[q] = fmaf(cl[l], sb[l][h], vv[q]);
            cs[q] += vv[q];
            cs2[q] += vv[q] * vv[q];
        }
        *(float4*)&g_Y[(size_t)r * HID + tx * 4] =
            make_float4(vv[0], vv[1], vv[2], vv[3]);
    }
    #pragma unroll
    for (int q = 0; q < 4; q++) {
        s_m[ty][tx * 4 + q] = cs[q];
        s_v[ty][tx * 4 + q] = cs2[q];
    }
    __syncthreads();
    if (tid < 64) {
        float s = 0.f, s2 = 0.f;
        #pragma unroll
        for (int g = 0; g < 16; g++) { s += s_m[g][tid]; s2 += s_v[g][tid]; }
        g_part1[blockIdx.x * 64 + tid] = s;
        g_part1[NPB * 64 + blockIdx.x * 64 + tid] = s2;
    }
}

// ---------------- K4: out_pre = [x | bnrelu(y_pre)] @ [W1; W2] + biases ----
// BM=64, BN=128, BK=16, 256 threads, f32x2. grid = 256 blocks.
__global__ __launch_bounds__(256) void k4_gemm(
    const float* __restrict__ x,
    const float* __restrict__ w1,  const float* __restrict__ w2,
    const float* __restrict__ b1w, const float* __restrict__ b2w,
    const float* __restrict__ gam1, const float* __restrict__ bet1,
    float* __restrict__ out)
{
    __shared__ float Asd[16][130];
    __shared__ float Bsp[16][128];
    __shared__ float s_scale[64], s_shift[64], s_bias[128];
    __shared__ float s_red[4][64], s_red2[4][64];
    __shared__ float s_m[16][128], s_v[16][128];

    const int tid = threadIdx.x;
    const int r0  = blockIdx.x * 64;

    // prologue: reduce BN1 partials (NPB k2 blocks)
    {
        const int ch = tid & 63, q = tid >> 6;
        float s = 0.f, s2 = 0.f;
        #pragma unroll
        for (int b = q * 64; b < q * 64 + 64; b++) {
            s  += g_part1[b * 64 + ch];
            s2 += g_part1[NPB * 64 + b * 64 + ch];
        }
        s_red[q][ch] = s; s_red2[q][ch] = s2;
        if (tid < 128) s_bias[tid] = b1w[tid] + b2w[tid];
        __syncthreads();
        if (tid < 64) {
            const float ss  = s_red[0][tid] + s_red[1][tid] + s_red[2][tid] + s_red[3][tid];
            const float ss2 = s_red2[0][tid] + s_red2[1][tid] + s_red2[2][tid] + s_red2[3][tid];
            const float mean = ss * (1.f / (float)N_NODES);
            const float var  = ss2 * (1.f / (float)N_NODES) - mean * mean;
            const float sc = rsqrtf(var + EPS) * gam1[tid];
            s_scale[tid] = sc;
            s_shift[tid] = bet1[tid] - mean * sc;
        }
    }

    const int tx = tid & 15;   // col group of 8
    const int ty = tid >> 4;   // row group of 4
    const int lkk = tid & 15, lm = tid >> 4;
    ull acc[4][4];
    #pragma unroll
    for (int i = 0; i < 4; i++)
        #pragma unroll
        for (int j = 0; j < 4; j++) acc[i][j] = 0ULL;

    for (int k0 = 0; k0 < 128; k0 += 16) {
        const bool xhalf = (k0 < 64);
        __syncthreads();
        #pragma unroll
        for (int jj = 0; jj < 4; jj++) {
            const int m = lm + 16 * jj;
            float v;
            if (xhalf) {
                v = x[(size_t)(r0 + m) * CIN + k0 + lkk];
            } else {
                const int c = k0 + lkk - 64;
                v = g_Y[(size_t)(r0 + m) * HID + c];
                v = fmaxf(fmaf(v, s_scale[c], s_shift[c]), 0.f);
            }
            *(float2*)&Asd[lkk][2 * m] = make_float2(v, v);
        }
        #pragma unroll
        for (int i = tid; i < 2048; i += 256) {
            const int r = i >> 7, h = i & 127;
            const float v = xhalf ? w1[(k0 + r) * OUTC + h]
                                  : w2[(k0 + r - 64) * OUTC + h];
            Bsp[r][((h & 7) >> 1) * 32 + (h >> 3) * 2 + (h & 1)] = v;
        }
        __syncthreads();
        #pragma unroll
        for (int kk = 0; kk < 16; kk++) {
            const ull* ap = (const ull*)&Asd[kk][0];
            const ull* bp = (const ull*)&Bsp[kk][0];
            ull a0 = ap[ty * 4 + 0], a1 = ap[ty * 4 + 1];
            ull a2 = ap[ty * 4 + 2], a3 = ap[ty * 4 + 3];
            #pragma unroll
            for (int jp = 0; jp < 4; jp++) {
                const ull b = bp[jp * 16 + tx];
                ffma2(acc[0][jp], a0, b);
                ffma2(acc[1][jp], a1, b);
                ffma2(acc[2][jp], a2, b);
                ffma2(acc[3][jp], a3, b);
            }
        }
    }

    // epilogue: bias, store, BN2 partials
    float cs[8], cs2[8];
    #pragma unroll
    for (int q = 0; q < 8; q++) { cs[q] = 0.f; cs2[q] = 0.f; }
    #pragma unroll
    for (int i = 0; i < 4; i++) {
        const int r = r0 + ty * 4 + i;
        float vv[8];
        #pragma unroll
        for (int jp = 0; jp < 4; jp++) {
            const float2 v = unpk(acc[i][jp]);
            vv[jp * 2]     = v.x;
            vv[jp * 2 + 1] = v.y;
        }
        #pragma unroll
        for (int q = 0; q < 8; q++) {
            vv[q] += s_bias[tx * 8 + q];
            cs[q] += vv[q];
            cs2[q] += vv[q] * vv[q];
        }
        float* op = out + (size_t)r * OUTC + tx * 8;
        *(float4*)op       = make_float4(vv[0], vv[1], vv[2], vv[3]);
        *(float4*)(op + 4) = make_float4(vv[4], vv[5], vv[6], vv[7]);
    }
    #pragma unroll
    for (int q = 0; q < 8; q++) {
        s_m[ty][tx * 8 + q] = cs[q];
        s_v[ty][tx * 8 + q] = cs2[q];
    }
    __syncthreads();
    if (tid < 128) {
        float s = 0.f, s2 = 0.f;
        #pragma unroll
        for (int g = 0; g < 16; g++) { s += s_m[g][tid]; s2 += s_v[g][tid]; }
        g_part2[blockIdx.x * 128 + tid] = s;
        g_part2[NPB * 128 + blockIdx.x * 128 + tid] = s2;
    }
}

// ---------------- K6: reduce BN2 partials + BN + relu ----------------
// grid = 128 blocks, 1024 threads; each block handles 128 rows.
__global__ __launch_bounds__(1024) void k6_final(
    float* __restrict__ out,
    const float* __restrict__ gam2, const float* __restrict__ bet2)
{
    __shared__ float s_sc[128], s_sh[128];
    __shared__ float s_r[8][128], s_r2[8][128];

    const int tid = threadIdx.x;
    const int ch = tid & 127, q = tid >> 7;   // q = 0..7
    float s = 0.f, s2 = 0.f;
    #pragma unroll
    for (int b = q * 32; b < q * 32 + 32; b++) {
        s  += g_part2[b * 128 + ch];
        s2 += g_part2[NPB * 128 + b * 128 + ch];
    }
    s_r[q][ch] = s; s_r2[q][ch] = s2;
    __syncthreads();
    if (tid < 128) {
        float ss = 0.f, ss2 = 0.f;
        #pragma unroll
        for (int g = 0; g < 8; g++) { ss += s_r[g][tid]; ss2 += s_r2[g][tid]; }
        const float mean = ss * (1.f / (float)N_NODES);
        const float var  = ss2 * (1.f / (float)N_NODES) - mean * mean;
        const float sc = rsqrtf(var + EPS) * gam2[tid];
        s_sc[tid] = sc;
        s_sh[tid] = bet2[tid] - mean * sc;
    }
    __syncthreads();

    float4* o4 = (float4*)(out + (size_t)blockIdx.x * 128 * OUTC);
    #pragma unroll
    for (int i = tid; i < 128 * 32; i += 1024) {
        const int c = (i & 31) * 4;
        float4 v = o4[i];
        v.x = fmaxf(fmaf(v.x, s_sc[c + 0], s_sh[c + 0]), 0.f);
        v.y = fmaxf(fmaf(v.y, s_sc[c + 1], s_sh[c + 1]), 0.f);
        v.z = fmaxf(fmaf(v.z, s_sc[c + 2], s_sh[c + 2]), 0.f);
        v.w = fmaxf(fmaf(v.w, s_sc[c + 3], s_sh[c + 3]), 0.f);
        o4[i] = v;
    }
}

// ---------------- launcher ----------------
extern "C" void kernel_launch(void* const* d_in, const int* in_sizes, int n_in,
                              void* d_out, int out_size)
{
    const float* x   = (const float*)d_in[0];
    const float* p   = (const float*)d_in[1];
    const int*   sid = (const int*)d_in[2];
    // d_in[3] = tid_euc (implicit arange/k grouping; unused)

    int o = 4;
    if (n_in >= 16 && in_sizes[4] == 1) o = 6;

    const float* lins_W = (const float*)d_in[o];
    const float* lins_b = (const float*)d_in[o + 1];
    const float* lin1_W = (const float*)d_in[o + 2];
    const float* lin1_b = (const float*)d_in[o + 3];
    const float* lin2_W = (const float*)d_in[o + 4];
    const float* lin2_b = (const float*)d_in[o + 5];
    const float* g1     = (const float*)d_in[o + 6];
    const float* b1     = (const float*)d_in[o + 7];
    const float* g2     = (const float*)d_in[o + 8];
    const float* b2     = (const float*)d_in[o + 9];
    float* out = (float*)d_out;

    k1_edge<<<N_NODES / 4, 256>>>(x, p, sid);
    k2_gemm<<<N_NODES / 64, 256>>>(lins_W, lins_b);
    k4_gemm<<<N_NODES / 64, 256>>>(x, lin1_W, lin2_W, lin1_b, lin2_b, g1, b1, out);
    k6_final<<<N_NODES / 128, 1024>>>(out, g2, b2);
}

// round 8
// speedup vs baseline: 1.6738x; 1.0906x over previous
#include <cuda_runtime.h>
#include <cuda_bf16.h>

typedef unsigned long long ull;

// Problem constants (fixed by the dataset)
#define N_NODES 16384      // B*n = 8*2048
#define K_EDGE  16
#define CIN     64
#define HID     64
#define OUTC    128
#define L6      6
#define KV      384        // 6*64
#define EPS     1e-5f

// ---------------- scratch (device globals; no allocations) ----------------
__device__ float g_V[N_NODES * KV];        // [t][l*64+c]
__device__ float g_Cl[N_NODES * L6];       // per-target coefficient sums
__device__ float g_Y[N_NODES * HID];       // y_pre (before BN1)
__device__ float g_part1[2 * 128 * HID];   // per-k2-block BN partials (sum, sumsq)
__device__ float g_part2[2 * 128 * OUTC];  // per-k4-block BN partials
__device__ float g_bn2[2 * OUTC];          // folded scale/shift for BN2

// ---------------- helpers ----------------
__device__ __forceinline__ void ffma2(ull& d, ull a, ull b) {
    asm("fma.rn.f32x2 %0, %1, %2, %3;" : "=l"(d) : "l"(a), "l"(b), "l"(d));
}
__device__ __forceinline__ ull dup2(float v) {
    ull r; asm("mov.b64 %0, {%1, %1};" : "=l"(r) : "f"(v)); return r;
}
__device__ __forceinline__ float2 unpk(ull v) {
    float2 r; asm("mov.b64 {%0, %1}, %2;" : "=f"(r.x), "=f"(r.y) : "l"(v)); return r;
}
__device__ __forceinline__ void cp4(void* smem_dst, const void* gsrc) {
    unsigned d = (unsigned)__cvta_generic_to_shared(smem_dst);
    asm volatile("cp.async.ca.shared.global [%0], [%1], 4;" :: "r"(d), "l"(gsrc));
}
__device__ __forceinline__ void cp_commit() { asm volatile("cp.async.commit_group;"); }
__device__ __forceinline__ void cp_wait0()  { asm volatile("cp.async.wait_group 0;" ::: "memory"); }

// ---------------- K1: per-target edge phase (R5-proven) ----------------
// grid = N_NODES/4 blocks, 256 threads (4 targets per block).
__global__ __launch_bounds__(256) void k1_edge(
    const float* __restrict__ x, const float* __restrict__ p,
    const int* __restrict__ sid)
{
    __shared__ float s_coef[4][K_EDGE][8];
    __shared__ int   s_sid[4][K_EDGE];

    const int tid  = threadIdx.x;
    const int w    = tid >> 5;
    const int lane = tid & 31;

    if (w < 4) {
        const int t   = blockIdx.x * 4 + w;
        const int j   = lane & 15;
        const bool act = lane < 16;
        const int s   = sid[t * K_EDGE + j];

        float dx = 0.f, dy = 0.f, dz = 0.f, dis = 0.f;
        if (act) {
            const float px = p[t*3+0], py = p[t*3+1], pz = p[t*3+2];
            dx = p[s*3+0] - px;
            dy = p[s*3+1] - py;
            dz = p[s*3+2] - pz;
            dis = fmaxf(sqrtf(dx*dx + dy*dy + dz*dz), 1e-16f);
            s_sid[w][j] = s;
        }
        float m = dis;
        #pragma unroll
        for (int off = 16; off; off >>= 1)
            m = fmaxf(m, __shfl_xor_sync(0xffffffffu, m, off));
        const float pr  = 1.1f * m;
        float pdv = act ? (pr - dis) * (pr - dis) : 0.f;
        float ssum = pdv;
        #pragma unroll
        for (int off = 16; off; off >>= 1)
            ssum += __shfl_xor_sync(0xffffffffu, ssum, off);

        if (act) {
            const float wgt = pdv / ssum;
            const float inv = 1.f / dis;
            const float c0 = cosf(dx * inv);
            const float c1 = cosf(dy * inv);
            const float c2 = cosf(dz * inv);
            float a[6] = {0.f, 0.f, 0.f, 0.f, 0.f, 0.f};
            a[    ((dx > 0.f) ? 1 : 0)] = c0 * c0;
            a[2 + ((dy > 0.f) ? 1 : 0)] = c1 * c1;
            a[4 + ((dz > 0.f) ? 1 : 0)] = c2 * c2;
            #pragma unroll
            for (int l = 0; l < 6; l++) s_coef[w][j][l] = wgt * a[l];
        }
    }
    __syncthreads();

    if (tid < 24) {
        const int tw = tid / 6, l = tid - tw * 6;
        float cl = 0.f;
        #pragma unroll
        for (int j = 0; j < K_EDGE; j++) cl += s_coef[tw][j][l];
        g_Cl[(blockIdx.x * 4 + tw) * L6 + l] = cl;
    }

    const int grp = tid >> 6;
    const int c   = tid & 63;
    const int t   = blockIdx.x * 4 + grp;
    const float xt = x[t * CIN + c];
    float acc[6] = {0.f, 0.f, 0.f, 0.f, 0.f, 0.f};
    #pragma unroll
    for (int j = 0; j < K_EDGE; j++) {
        const float ev = x[s_sid[grp][j] * CIN + c] - xt;
        const float4 c01 = *(const float4*)&s_coef[grp][j][0];
        const float2 c2  = *(const float2*)&s_coef[grp][j][4];
        acc[0] = fmaf(c01.x, ev, acc[0]);
        acc[1] = fmaf(c01.y, ev, acc[1]);
        acc[2] = fmaf(c01.z, ev, acc[2]);
        acc[3] = fmaf(c01.w, ev, acc[3]);
        acc[4] = fmaf(c2.x,  ev, acc[4]);
        acc[5] = fmaf(c2.y,  ev, acc[5]);
    }
    float* vp = g_V + (size_t)t * KV + c;
    #pragma unroll
    for (int l = 0; l < 6; l++) vp[l * 64] = acc[l];
}

// ---------------- K2 v3: y_pre = V @ Wcat + Cl @ lins_b  (+ BN1 partials) --
// BM=128, BN=64, BK=16, 256 threads, cp.async double-buffered,
// pair-over-M f32x2 (A m-major raw, B dup-pairs). grid = 128 blocks.
__global__ __launch_bounds__(256) void k2_gemm(
    const float* __restrict__ W2,   // lins_W viewed as (384, 64)
    const float* __restrict__ lb)   // lins_b (6, 64)
{
    __shared__ float As[2][16 * 130];   // [st][kk*130 + m] raw A, m-contiguous
    __shared__ ull   Bd[2][16 * 64];    // [st][kk*64 + (h&3)*16 + (h>>2)] dup pairs
    __shared__ float sb[6][64];
    __shared__ float s_m[16][64], s_v[16][64];

    const int tid = threadIdx.x;
    const int r0  = blockIdx.x * 128;
    for (int i = tid; i < 384; i += 256) sb[i >> 6][i & 63] = lb[i];

    const int tx  = tid & 15, ty = tid >> 4;     // compute: cols tx*4.., rows ty*8..
    const int lkk = tid & 15, lm0 = tid >> 4;    // A loader
    const int bq  = tid >> 6, bh = tid & 63;     // B loader

    // ---- prologue: tile 0 ----
    #pragma unroll
    for (int jj = 0; jj < 8; jj++) {
        const int m = lm0 + 16 * jj;
        cp4(&As[0][lkk * 130 + m], &g_V[(size_t)(r0 + m) * KV + lkk]);
    }
    cp_commit();
    float rb[4];
    #pragma unroll
    for (int jj = 0; jj < 4; jj++) rb[jj] = W2[(bq + 4 * jj) * 64 + bh];
    #pragma unroll
    for (int jj = 0; jj < 4; jj++)
        Bd[0][(bq + 4 * jj) * 64 + (bh & 3) * 16 + (bh >> 2)] = dup2(rb[jj]);
    cp_wait0();
    __syncthreads();

    ull acc[4][4];
    #pragma unroll
    for (int i = 0; i < 4; i++)
        #pragma unroll
        for (int j = 0; j < 4; j++) acc[i][j] = 0ULL;

    for (int s = 0; s < 24; s++) {
        const int st = s & 1;
        const bool more = (s < 23);
        if (more) {
            const int k0n = (s + 1) * 16;
            #pragma unroll
            for (int jj = 0; jj < 8; jj++) {
                const int m = lm0 + 16 * jj;
                cp4(&As[st ^ 1][lkk * 130 + m],
                    &g_V[(size_t)(r0 + m) * KV + k0n + lkk]);
            }
            cp_commit();
            #pragma unroll
            for (int jj = 0; jj < 4; jj++)
                rb[jj] = W2[(k0n + bq + 4 * jj) * 64 + bh];
        }
        #pragma unroll
        for (int kk = 0; kk < 16; kk++) {
            const ull* ap = (const ull*)&As[st][kk * 130];
            const ull* bp = &Bd[st][kk * 64];
            ull a0 = ap[ty * 4 + 0], a1 = ap[ty * 4 + 1];
            ull a2 = ap[ty * 4 + 2], a3 = ap[ty * 4 + 3];
            ull b0 = bp[tx], b1 = bp[16 + tx], b2 = bp[32 + tx], b3 = bp[48 + tx];
            ffma2(acc[0][0], a0, b0); ffma2(acc[0][1], a0, b1);
            ffma2(acc[0][2], a0, b2); ffma2(acc[0][3], a0, b3);
            ffma2(acc[1][0], a1, b0); ffma2(acc[1][1], a1, b1);
            ffma2(acc[1][2], a1, b2); ffma2(acc[1][3], a1, b3);
            ffma2(acc[2][0], a2, b0); ffma2(acc[2][1], a2, b1);
            ffma2(acc[2][2], a2, b2); ffma2(acc[2][3], a2, b3);
            ffma2(acc[3][0], a3, b0); ffma2(acc[3][1], a3, b1);
            ffma2(acc[3][2], a3, b2); ffma2(acc[3][3], a3, b3);
        }
        if (more) {
            #pragma unroll
            for (int jj = 0; jj < 4; jj++)
                Bd[st ^ 1][(bq + 4 * jj) * 64 + (bh & 3) * 16 + (bh >> 2)] = dup2(rb[jj]);
            cp_wait0();
        }
        __syncthreads();
    }

    // ---- epilogue: + Cl@lins_b, store y_pre, BN1 partials ----
    // acc[p][n] = ( C[ty*8+2p][tx*4+n], C[ty*8+2p+1][tx*4+n] )
    float cs[4] = {0.f, 0.f, 0.f, 0.f}, cs2[4] = {0.f, 0.f, 0.f, 0.f};
    #pragma unroll
    for (int pi = 0; pi < 4; pi++) {
        const int re = r0 + ty * 8 + 2 * pi;
        float2 v[4];
        #pragma unroll
        for (int n = 0; n < 4; n++) v[n] = unpk(acc[pi][n]);

        float cle[6], clo[6];
        #pragma unroll
        for (int l = 0; l < 6; l++) { cle[l] = g_Cl[re * L6 + l]; clo[l] = g_Cl[(re + 1) * L6 + l]; }

        float ve[4], vo[4];
        #pragma unroll
        for (int n = 0; n < 4; n++) {
            const int h = tx * 4 + n;
            float a = v[n].x, b = v[n].y;
            #pragma unroll
            for (int l = 0; l < 6; l++) {
                a = fmaf(cle[l], sb[l][h], a);
                b = fmaf(clo[l], sb[l][h], b);
            }
            ve[n] = a; vo[n] = b;
            cs[n]  += a + b;
            cs2[n] += a * a + b * b;
        }
        *(float4*)&g_Y[(size_t)re * HID + tx * 4] =
            make_float4(ve[0], ve[1], ve[2], ve[3]);
        *(float4*)&g_Y[(size_t)(re + 1) * HID + tx * 4] =
            make_float4(vo[0], vo[1], vo[2], vo[3]);
    }
    #pragma unroll
    for (int n = 0; n < 4; n++) {
        s_m[ty][tx * 4 + n] = cs[n];
        s_v[ty][tx * 4 + n] = cs2[n];
    }
    __syncthreads();
    if (tid < 64) {
        float s = 0.f, s2 = 0.f;
        #pragma unroll
        for (int g = 0; g < 16; g++) { s += s_m[g][tid]; s2 += s_v[g][tid]; }
        g_part1[blockIdx.x * 64 + tid] = s;
        g_part1[8192 + blockIdx.x * 64 + tid] = s2;
    }
}

// ---------------- K4: out_pre = [x | bnrelu(y_pre)] @ [W1; W2] + biases ----
// (R5-proven) BM=128, BN=128, BK=16, 256 threads, A-dup f32x2. grid = 128.
__global__ __launch_bounds__(256) void k4_gemm(
    const float* __restrict__ x,
    const float* __restrict__ w1,  const float* __restrict__ w2,
    const float* __restrict__ b1w, const float* __restrict__ b2w,
    const float* __restrict__ gam1, const float* __restrict__ bet1,
    float* __restrict__ out)
{
    __shared__ float Asd[16][258];
    __shared__ float Bsp[16][128];
    __shared__ float s_scale[64], s_shift[64], s_bias[128];
    __shared__ float s_red[4][64], s_red2[4][64];
    __shared__ float s_m[16][128], s_v[16][128];

    const int tid = threadIdx.x;
    const int r0  = blockIdx.x * 128;

    // prologue: reduce BN1 partials (128 k2 blocks)
    {
        const int ch = tid & 63, q = tid >> 6;
        float s = 0.f, s2 = 0.f;
        #pragma unroll
        for (int b = q * 32; b < q * 32 + 32; b++) {
            s  += g_part1[b * 64 + ch];
            s2 += g_part1[8192 + b * 64 + ch];
        }
        s_red[q][ch] = s; s_red2[q][ch] = s2;
        if (tid < 128) s_bias[tid] = b1w[tid] + b2w[tid];
        __syncthreads();
        if (tid < 64) {
            const float ss  = s_red[0][tid] + s_red[1][tid] + s_red[2][tid] + s_red[3][tid];
            const float ss2 = s_red2[0][tid] + s_red2[1][tid] + s_red2[2][tid] + s_red2[3][tid];
            const float mean = ss * (1.f / (float)N_NODES);
            const float var  = ss2 * (1.f / (float)N_NODES) - mean * mean;
            const float sc = rsqrtf(var + EPS) * gam1[tid];
            s_scale[tid] = sc;
            s_shift[tid] = bet1[tid] - mean * sc;
        }
    }

    const int tx = tid & 15;   // col group of 8
    const int ty = tid >> 4;   // row group of 8
    ull acc[8][4];
    #pragma unroll
    for (int i = 0; i < 8; i++)
        #pragma unroll
        for (int j = 0; j < 4; j++) acc[i][j] = 0ULL;

    for (int k0 = 0; k0 < 128; k0 += 16) {
        const bool xhalf = (k0 < 64);
        __syncthreads();
        #pragma unroll
        for (int i = tid; i < 2048; i += 256) {
            const int m = i >> 4, kk = i & 15;
            float v;
            if (xhalf) {
                v = x[(size_t)(r0 + m) * CIN + k0 + kk];
            } else {
                const int c = k0 + kk - 64;
                v = g_Y[(size_t)(r0 + m) * HID + c];
                v = fmaxf(fmaf(v, s_scale[c], s_shift[c]), 0.f);
            }
            *(float2*)&Asd[kk][2 * m] = make_float2(v, v);
        }
        #pragma unroll
        for (int i = tid; i < 2048; i += 256) {
            const int r = i >> 7, h = i & 127;
            const float v = xhalf ? w1[(k0 + r) * OUTC + h]
                                  : w2[(k0 + r - 64) * OUTC + h];
            Bsp[r][((h & 7) >> 1) * 32 + (h >> 3) * 2 + (h & 1)] = v;
        }
        __syncthreads();
        #pragma unroll
        for (int kk = 0; kk < 16; kk++) {
            const ull* ap = (const ull*)&Asd[kk][0];
            const ull* bp = (const ull*)&Bsp[kk][0];
            ull a[8], b[4];
            #pragma unroll
            for (int i = 0; i < 8; i++) a[i] = ap[ty * 8 + i];
            #pragma unroll
            for (int jp = 0; jp < 4; jp++) b[jp] = bp[jp * 16 + tx];
            #pragma unroll
            for (int i = 0; i < 8; i++)
                #pragma unroll
                for (int jp = 0; jp < 4; jp++)
                    ffma2(acc[i][jp], a[i], b[jp]);
        }
    }

    // epilogue: bias, store, BN2 partials
    float cs[8], cs2[8];
    #pragma unroll
    for (int q = 0; q < 8; q++) { cs[q] = 0.f; cs2[q] = 0.f; }
    #pragma unroll
    for (int i = 0; i < 8; i++) {
        const int r = r0 + ty * 8 + i;
        float vv[8];
        #pragma unroll
        for (int jp = 0; jp < 4; jp++) {
            const float2 v = unpk(acc[i][jp]);
            vv[jp * 2]     = v.x;
            vv[jp * 2 + 1] = v.y;
        }
        #pragma unroll
        for (int q = 0; q < 8; q++) {
            vv[q] += s_bias[tx * 8 + q];
            cs[q] += vv[q];
            cs2[q] += vv[q] * vv[q];
        }
        float* op = out + (size_t)r * OUTC + tx * 8;
        *(float4*)op       = make_float4(vv[0], vv[1], vv[2], vv[3]);
        *(float4*)(op + 4) = make_float4(vv[4], vv[5], vv[6], vv[7]);
    }
    #pragma unroll
    for (int q = 0; q < 8; q++) {
        s_m[ty][tx * 8 + q] = cs[q];
        s_v[ty][tx * 8 + q] = cs2[q];
    }
    __syncthreads();
    if (tid < 128) {
        float s = 0.f, s2 = 0.f;
        #pragma unroll
        for (int g = 0; g < 16; g++) { s += s_m[g][tid]; s2 += s_v[g][tid]; }
        g_part2[blockIdx.x * 128 + tid] = s;
        g_part2[16384 + blockIdx.x * 128 + tid] = s2;
    }
}

// ---------------- K5: BN2 stats (single block — partials read ONCE) --------
__global__ __launch_bounds__(1024) void k5_stats(
    const float* __restrict__ gam2, const float* __restrict__ bet2)
{
    __shared__ float s_r[8][128], s_r2[8][128];
    const int tid = threadIdx.x;
    const int ch = tid & 127, q = tid >> 7;   // q = 0..7, 16 blocks each
    float s = 0.f, s2 = 0.f;
    #pragma unroll
    for (int b = q * 16; b < q * 16 + 16; b++) {
        s  += g_part2[b * 128 + ch];
        s2 += g_part2[16384 + b * 128 + ch];
    }
    s_r[q][ch] = s; s_r2[q][ch] = s2;
    __syncthreads();
    if (tid < 128) {
        float ss = 0.f, ss2 = 0.f;
        #pragma unroll
        for (int g = 0; g < 8; g++) { ss += s_r[g][tid]; ss2 += s_r2[g][tid]; }
        const float mean = ss * (1.f / (float)N_NODES);
        const float var  = ss2 * (1.f / (float)N_NODES) - mean * mean;
        const float sc = rsqrtf(var + EPS) * gam2[tid];
        g_bn2[tid] = sc;
        g_bn2[128 + tid] = bet2[tid] - mean * sc;
    }
}

// ---------------- K6: pure elementwise BN + relu ----------------
// grid = 256 blocks, 256 threads; each block handles 64 rows (2048 float4).
__global__ __launch_bounds__(256) void k6_elem(float* __restrict__ out)
{
    __shared__ float s_sc[128], s_sh[128];
    const int tid = threadIdx.x;
    if (tid < 128) { s_sc[tid] = g_bn2[tid]; s_sh[tid] = g_bn2[128 + tid]; }
    __syncthreads();

    float4* o4 = (float4*)(out + (size_t)blockIdx.x * 64 * OUTC);
    #pragma unroll
    for (int i = tid; i < 64 * 32; i += 256) {
        const int c = (i & 31) * 4;
        float4 v = o4[i];
        v.x = fmaxf(fmaf(v.x, s_sc[c + 0], s_sh[c + 0]), 0.f);
        v.y = fmaxf(fmaf(v.y, s_sc[c + 1], s_sh[c + 1]), 0.f);
        v.z = fmaxf(fmaf(v.z, s_sc[c + 2], s_sh[c + 2]), 0.f);
        v.w = fmaxf(fmaf(v.w, s_sc[c + 3], s_sh[c + 3]), 0.f);
        o4[i] = v;
    }
}

// ---------------- launcher ----------------
extern "C" void kernel_launch(void* const* d_in, const int* in_sizes, int n_in,
                              void* d_out, int out_size)
{
    const float* x   = (const float*)d_in[0];
    const float* p   = (const float*)d_in[1];
    const int*   sid = (const int*)d_in[2];
    // d_in[3] = tid_euc (implicit arange/k grouping; unused)

    int o = 4;
    if (n_in >= 16 && in_sizes[4] == 1) o = 6;

    const float* lins_W = (const float*)d_in[o];
    const float* lins_b = (const float*)d_in[o + 1];
    const float* lin1_W = (const float*)d_in[o + 2];
    const float* lin1_b = (const float*)d_in[o + 3];
    const float* lin2_W = (const float*)d_in[o + 4];
    const float* lin2_b = (const float*)d_in[o + 5];
    const float* g1     = (const float*)d_in[o + 6];
    const float* b1     = (const float*)d_in[o + 7];
    const float* g2     = (const float*)d_in[o + 8];
    const float* b2     = (const float*)d_in[o + 9];
    float* out = (float*)d_out;

    k1_edge<<<N_NODES / 4, 256>>>(x, p, sid);
    k2_gemm<<<N_NODES / 128, 256>>>(lins_W, lins_b);
    k4_gemm<<<N_NODES / 128, 256>>>(x, lin1_W, lin2_W, lin1_b, lin2_b, g1, b1, out);
    k5_stats<<<1, 1024>>>(g2, b2);
    k6_elem<<<N_NODES / 64, 256>>>(out);
}